// round 16
// baseline (speedup 1.0000x reference)
#include <cuda_runtime.h>

// ButterflyTransform: x[8192,4096] fp32, W[12,2048,2,2] fp32.
// All 12 layers pair adjacent elements identically -> per pair n the network
// collapses to one composed 2x2 matrix M[n] = W0[n]@...@W11[n]  (y = x*W).
// Phase 1: tiny compose kernel (hoisted loads). Phase 2: streaming apply.
// Apply is tuned for max DRAM: 32 regs -> 8 blocks/SM (64 warps), RB=2
// read/write batching, evict-first loads, pointer-bump addressing.

#define BATCH   8192
#define SIZE    4096
#define NPAIRS  (SIZE / 2)        // 2048
#define LOG_N   12
#define F4_PER_ROW (SIZE / 4)     // 1024 float4 per row

// Composed matrices: (m00, m01, m10, m11) per pair. 32 KB scratch.
__device__ float4 g_M[NPAIRS];

__global__ void compose_kernel(const float* __restrict__ W) {
    int n = blockIdx.x * blockDim.x + threadIdx.x;
    if (n >= NPAIRS) return;
    const float4* __restrict__ Wl = reinterpret_cast<const float4*>(W);  // [l][pair]

    float4 w[LOG_N];
#pragma unroll
    for (int l = 0; l < LOG_N; l++)
        w[l] = Wl[l * NPAIRS + n];

    float4 m = w[0];
#pragma unroll
    for (int l = 1; l < LOG_N; l++) {
        float4 t;
        t.x = fmaf(m.x, w[l].x, m.y * w[l].z);
        t.y = fmaf(m.x, w[l].y, m.y * w[l].w);
        t.z = fmaf(m.z, w[l].x, m.w * w[l].z);
        t.w = fmaf(m.z, w[l].y, m.w * w[l].w);
        m = t;
    }
    g_M[n] = m;
}

#define ROWS_PER_BLOCK 16
#define TPB 256

__device__ __forceinline__ float4 bfly(float4 v, float4 mA, float4 mB) {
    float4 o;
    o.x = fmaf(v.x, mA.x, v.y * mA.z);
    o.y = fmaf(v.x, mA.y, v.y * mA.w);
    o.z = fmaf(v.z, mB.x, v.w * mB.z);
    o.w = fmaf(v.z, mB.y, v.w * mB.w);
    return o;
}

__global__ void __launch_bounds__(TPB, 8)    // force <=32 regs -> 64 warps/SM
apply_kernel(const float* __restrict__ x, float* __restrict__ out) {
    const int col4 = blockIdx.x * TPB + threadIdx.x;      // 0..1023
    const float4 mA = g_M[2 * col4];
    const float4 mB = g_M[2 * col4 + 1];

    const float4* __restrict__ xp =
        reinterpret_cast<const float4*>(x) +
        (size_t)blockIdx.y * ROWS_PER_BLOCK * F4_PER_ROW + col4;
    float4* __restrict__ yp =
        reinterpret_cast<float4*>(out) +
        (size_t)blockIdx.y * ROWS_PER_BLOCK * F4_PER_ROW + col4;

#pragma unroll
    for (int r = 0; r < ROWS_PER_BLOCK; r += 2) {
        // batch 2 loads, then 2 stores: fewer HBM read<->write turnarounds
        float4 v0 = __ldcs(xp);
        float4 v1 = __ldcs(xp + F4_PER_ROW);
        float4 o0 = bfly(v0, mA, mB);
        float4 o1 = bfly(v1, mA, mB);
        yp[0]          = o0;
        yp[F4_PER_ROW] = o1;
        xp += 2 * F4_PER_ROW;
        yp += 2 * F4_PER_ROW;
    }
}

extern "C" void kernel_launch(void* const* d_in, const int* in_sizes, int n_in,
                              void* d_out, int out_size) {
    const float* x = (const float*)d_in[0];   // [8192, 4096]
    const float* W = (const float*)d_in[1];   // [12, 2048, 2, 2]
    float* out = (float*)d_out;

    compose_kernel<<<32, 64>>>(W);            // 2048 threads over 32 blocks

    dim3 grid(F4_PER_ROW / TPB, BATCH / ROWS_PER_BLOCK);  // (4, 512)
    apply_kernel<<<grid, TPB>>>(x, out);
}